// round 4
// baseline (speedup 1.0000x reference)
#include <cuda_runtime.h>

// InteractionArch: B x (1 dense + 26 sparse) x 128 -> strict upper triangle of
// per-row Gram matrix (27x27 -> 351 entries).
//
// One warp (= one block) handles THREE batch rows; K=128 is processed in
// TWO stages of 64 so the smem footprint is 21.5 KB -> 10 blocks/SM
// (vs 43 KB -> 5 blocks/SM previously; the kernel was latency-bound).
//
// 27x27 Gram triangle covered by the 10 upper 7x7 tiles of a 4x4 tile grid;
// 3 rows x 10 tiles = 30 lanes (lanes 30,31 mirror, write-masked).
//
// Swizzle: float4-chunk c (within stage, 0..15) of row r in buffer w sits at
// position (c + 3r + w) & 15. Bank quad = position & 7; since 3*7 = 21 = 5
// (mod 8) generates the full group, every octet phase of every LDS touches
// pairwise-distinct bank quads (duplicates are same-address broadcasts).
//
// Accumulation: packed fma.rn.f32x2 (98 FFMA2 + 14 LDS.128 per k-chunk).

#define FEAT 27
#define DIM 128
#define NPAIR 351
#define ROWS 28             // padded rows per batch (row 27 zero)
#define SCH 16              // float4 chunks per row per stage
#define RSTRIDE 64          // floats per row per stage
#define BUFF (ROWS * RSTRIDE)   // 1792 floats per batch row
#define RPW 3               // batch rows per warp
#define STAGES 2

__device__ __forceinline__ void fma2(unsigned long long& d,
                                     unsigned long long a,
                                     unsigned long long b) {
    asm("fma.rn.f32x2 %0, %1, %2, %0;" : "+l"(d) : "l"(a), "l"(b));
}

__device__ __forceinline__ float hsum2(unsigned long long p) {
    unsigned int lo, hi;
    asm("mov.b64 {%0, %1}, %2;" : "=r"(lo), "=r"(hi) : "l"(p));
    return __uint_as_float(lo) + __uint_as_float(hi);
}

__global__ __launch_bounds__(32, 10)
void interaction_kernel(const float* __restrict__ dense,
                        const float* __restrict__ sparse,
                        float* __restrict__ out,
                        int B)
{
    __shared__ float A[RPW * BUFF];   // 21504 bytes

    const int lane = threadIdx.x;     // blockDim = 32
    const long bbase = (long)blockIdx.x * RPW;

    // ---- Lane -> (buffer w, tile t); tiles: (0,0)(0,1)(0,2)(0,3)(1,1)(1,2)(1,3)(2,2)(2,3)(3,3)
    const int lw = (lane < 30) ? lane : 29;
    const int w  = lw / 10;
    const int t  = lw % 10;
    const int ti = (t >= 4) + (t >= 7) + (t >= 9);
    const int start = 4 * ti - ((ti * (ti - 1)) >> 1);
    const int tj = ti + (t - start);
    const int i0 = 7 * ti;
    const int j0 = 7 * tj;

    // consecutive tile rows => offsets are base + x*RSTRIDE, salts salt0 + 3x
    const int abase = w * BUFF + i0 * RSTRIDE;
    const int cbase = w * BUFF + j0 * RSTRIDE;
    const int asalt = 3 * i0 + w;
    const int csalt = 3 * j0 + w;

    unsigned long long acc[49] = {};   // acc[x*7+y], packed f32x2 partial sums

#pragma unroll
    for (int s = 0; s < STAGES; ++s) {
        // ---- Load phase: 28 rows x 16 chunks per buffer, 14 LDG.128/lane/buffer
#pragma unroll
        for (int w2 = 0; w2 < RPW; ++w2) {
            const long b = bbase + w2;
            if (b < B) {
                float* buf = A + w2 * BUFF;
                const float* drow = dense + b * DIM + s * RSTRIDE;
                const float* sbase = sparse + (b * 26) * DIM + s * RSTRIDE;
#pragma unroll
                for (int q = 0; q < 14; ++q) {
                    const int id = q * 32 + lane;
                    const int row = id >> 4;
                    const int cc = id & 15;
                    float4 v;
                    if (row == 0)
                        v = *reinterpret_cast<const float4*>(drow + cc * 4);
                    else if (row <= 26)
                        v = *reinterpret_cast<const float4*>(sbase + (size_t)(row - 1) * DIM + cc * 4);
                    else
                        v = make_float4(0.f, 0.f, 0.f, 0.f);
                    const int pos = (cc + 3 * row + w2) & 15;
                    *reinterpret_cast<float4*>(buf + row * RSTRIDE + (pos << 2)) = v;
                }
            }
        }
        __syncwarp();

        // ---- Compute phase: 16 k-chunks of this stage
#pragma unroll 4
        for (int c = 0; c < SCH; ++c) {
            ulonglong2 av[7];
#pragma unroll
            for (int x = 0; x < 7; ++x)
                av[x] = *reinterpret_cast<const ulonglong2*>(
                    A + abase + x * RSTRIDE + (((c + asalt + 3 * x) & 15) << 2));
#pragma unroll
            for (int y = 0; y < 7; ++y) {
                ulonglong2 cv = *reinterpret_cast<const ulonglong2*>(
                    A + cbase + y * RSTRIDE + (((c + csalt + 3 * y) & 15) << 2));
#pragma unroll
                for (int x = 0; x < 7; ++x) {
                    fma2(acc[x * 7 + y], av[x].x, cv.x);
                    fma2(acc[x * 7 + y], av[x].y, cv.y);
                }
            }
        }
        __syncwarp();   // everyone done reading before next stage overwrites
    }

    // ---- Stage results into smem (buffer w reused as staging) ----
    if (lane < 30 && bbase + w < B) {
        float* stg = A + w * BUFF;
#pragma unroll
        for (int x = 0; x < 7; ++x) {
#pragma unroll
            for (int y = 0; y < 7; ++y) {
                const int i = i0 + x;
                const int j = j0 + y;
                if (i < j && j < FEAT) {
                    const int idx = i * (2 * FEAT - i - 1) / 2 + (j - i - 1);
                    stg[idx] = hsum2(acc[x * 7 + y]);
                }
            }
        }
    }
    __syncwarp();

    // ---- Coalesced writeout ----
#pragma unroll
    for (int ww = 0; ww < RPW; ++ww) {
        const long b = bbase + ww;
        if (b < B) {
            const float* stg = A + ww * BUFF;
            float* ob = out + b * NPAIR;
#pragma unroll
            for (int it = 0; it < 11; ++it) {
                const int idx = it * 32 + lane;
                if (idx < NPAIR) ob[idx] = stg[idx];
            }
        }
    }
}

extern "C" void kernel_launch(void* const* d_in, const int* in_sizes, int n_in,
                              void* d_out, int out_size)
{
    const float* dense  = (const float*)d_in[0];   // (B, 128)
    const float* sparse = (const float*)d_in[1];   // (B, 26, 128)
    float* out = (float*)d_out;                    // (B, 351)

    const int B = in_sizes[0] / DIM;
    const int grid = (B + RPW - 1) / RPW;
    interaction_kernel<<<grid, 32>>>(dense, sparse, out, B);
}

// round 5
// speedup vs baseline: 1.3889x; 1.3889x over previous
#include <cuda_runtime.h>

// InteractionArch: B x (1 dense + 26 sparse) x 128 -> strict upper triangle of
// per-row Gram matrix (27x27 -> 351 entries).
//
// One warp (= one block) handles THREE batch rows; K=128 processed in TWO
// stages of 64 -> smem 21.5 KB -> 10 blocks/SM. NO min-blocks launch bound:
// round 4 proved that forcing regs to 168 spills the 98-register accumulator
// set and regresses badly. Natural allocation (~220 regs) still allows 10
// blocks/SM (262144 regs/SM / (222*32) = 36 blocks).
//
// 27x27 Gram triangle covered by the 10 upper 7x7 tiles of a 4x4 tile grid;
// 3 rows x 10 tiles = 30 lanes (lanes 30,31 mirror lane 29, write-masked).
//
// Swizzle: float4-chunk c (0..15 within stage) of row r in buffer w sits at
// chunk position (c + 3r + w) & 15. Bank quad = position & 7; 3*7 = 21 = 5
// (mod 8) generates the full group, so every octet phase of every LDS.128
// touches pairwise-distinct bank quads (duplicates are broadcasts) --
// verified lane-by-lane for all four phases of both av and cv loads.
//
// Accumulation: packed fma.rn.f32x2 (98 FFMA2 + 14 LDS.128 per 16B k-chunk).

#define FEAT 27
#define DIM 128
#define NPAIR 351
#define ROWS 28              // padded rows per batch (row 27 zero)
#define SCH 16               // float4 chunks per row per stage
#define RSTRIDE 64           // floats per row per stage
#define BUFF (ROWS * RSTRIDE)    // 1792 floats per batch-row buffer
#define RPW 3                // batch rows per warp
#define STAGES 2

__device__ __forceinline__ void fma2(unsigned long long& d,
                                     unsigned long long a,
                                     unsigned long long b) {
    asm("fma.rn.f32x2 %0, %1, %2, %0;" : "+l"(d) : "l"(a), "l"(b));
}

__device__ __forceinline__ float hsum2(unsigned long long p) {
    unsigned int lo, hi;
    asm("mov.b64 {%0, %1}, %2;" : "=r"(lo), "=r"(hi) : "l"(p));
    return __uint_as_float(lo) + __uint_as_float(hi);
}

__global__ __launch_bounds__(32)
void interaction_kernel(const float* __restrict__ dense,
                        const float* __restrict__ sparse,
                        float* __restrict__ out,
                        int B)
{
    __shared__ float A[RPW * BUFF];   // 21504 bytes

    const int lane = threadIdx.x;     // blockDim = 32
    const long bbase = (long)blockIdx.x * RPW;

    // ---- Lane -> (buffer w, tile t); tiles: (0,0)(0,1)(0,2)(0,3)(1,1)(1,2)(1,3)(2,2)(2,3)(3,3)
    const int lw = (lane < 30) ? lane : 29;
    const int w  = lw / 10;
    const int t  = lw % 10;
    const int ti = (t >= 4) + (t >= 7) + (t >= 9);
    const int start = 4 * ti - ((ti * (ti - 1)) >> 1);
    const int tj = ti + (t - start);
    const int i0 = 7 * ti;
    const int j0 = 7 * tj;

    const int abase = w * BUFF + i0 * RSTRIDE;
    const int cbase = w * BUFF + j0 * RSTRIDE;
    const int asalt = 3 * i0 + w;
    const int csalt = 3 * j0 + w;

    // load-phase lane decomposition (branchless sparse loads, 2 rows/instr)
    const int lrow = lane >> 4;       // 0 or 1
    const int lchk = lane & 15;       // chunk within stage

    unsigned long long acc[49] = {};  // acc[x*7+y], packed f32x2 partial sums

#pragma unroll
    for (int s = 0; s < STAGES; ++s) {
        // ---- Load phase: 28 rows x 16 chunks per buffer ----
#pragma unroll
        for (int w2 = 0; w2 < RPW; ++w2) {
            const long b = bbase + w2;
            if (b < B) {
                float* buf = A + w2 * BUFF;
                // dense row (row 0): half-warp, 256B coalesced
                if (lane < 16) {
                    float4 v = *reinterpret_cast<const float4*>(
                        dense + b * DIM + s * RSTRIDE + lane * 4);
                    *reinterpret_cast<float4*>(
                        buf + (((lane + w2) & 15) << 2)) = v;
                }
                // sparse rows 1..26: 13 iterations, rows (1+2q+lrow)
                const float* sbase = sparse + (b * 26) * DIM + s * RSTRIDE;
#pragma unroll
                for (int q = 0; q < 13; ++q) {
                    const int row = 1 + 2 * q + lrow;
                    float4 v = *reinterpret_cast<const float4*>(
                        sbase + (size_t)(row - 1) * DIM + lchk * 4);
                    const int pos = (lchk + 3 * row + w2) & 15;
                    *reinterpret_cast<float4*>(
                        buf + row * RSTRIDE + (pos << 2)) = v;
                }
                // zero pad row 27 (half-warp)
                if (lane < 16) {
                    *reinterpret_cast<float4*>(
                        buf + 27 * RSTRIDE + (((lane + 81 + w2) & 15) << 2)) =
                        make_float4(0.f, 0.f, 0.f, 0.f);
                }
            }
        }
        __syncwarp();

        // ---- Compute phase: 16 k-chunks of this stage ----
#pragma unroll 4
        for (int c = 0; c < SCH; ++c) {
            ulonglong2 av[7];
#pragma unroll
            for (int x = 0; x < 7; ++x)
                av[x] = *reinterpret_cast<const ulonglong2*>(
                    A + abase + x * RSTRIDE + (((c + asalt + 3 * x) & 15) << 2));
#pragma unroll
            for (int y = 0; y < 7; ++y) {
                ulonglong2 cv = *reinterpret_cast<const ulonglong2*>(
                    A + cbase + y * RSTRIDE + (((c + csalt + 3 * y) & 15) << 2));
#pragma unroll
                for (int x = 0; x < 7; ++x) {
                    fma2(acc[x * 7 + y], av[x].x, cv.x);
                    fma2(acc[x * 7 + y], av[x].y, cv.y);
                }
            }
        }
        __syncwarp();   // all reads done before next stage overwrites
    }

    // ---- Stage results into smem (buffer w reused as staging) ----
    if (lane < 30 && bbase + w < B) {
        float* stg = A + w * BUFF;
#pragma unroll
        for (int x = 0; x < 7; ++x) {
#pragma unroll
            for (int y = 0; y < 7; ++y) {
                const int i = i0 + x;
                const int j = j0 + y;
                if (i < j && j < FEAT) {
                    const int idx = i * (2 * FEAT - i - 1) / 2 + (j - i - 1);
                    stg[idx] = hsum2(acc[x * 7 + y]);
                }
            }
        }
    }
    __syncwarp();

    // ---- Coalesced writeout ----
#pragma unroll
    for (int ww = 0; ww < RPW; ++ww) {
        const long b = bbase + ww;
        if (b < B) {
            const float* stg = A + ww * BUFF;
            float* ob = out + b * NPAIR;
#pragma unroll
            for (int it = 0; it < 11; ++it) {
                const int idx = it * 32 + lane;
                if (idx < NPAIR) ob[idx] = stg[idx];
            }
        }
    }
}

extern "C" void kernel_launch(void* const* d_in, const int* in_sizes, int n_in,
                              void* d_out, int out_size)
{
    const float* dense  = (const float*)d_in[0];   // (B, 128)
    const float* sparse = (const float*)d_in[1];   // (B, 26, 128)
    float* out = (float*)d_out;                    // (B, 351)

    const int B = in_sizes[0] / DIM;
    const int grid = (B + RPW - 1) / RPW;
    interaction_kernel<<<grid, 32>>>(dense, sparse, out, B);
}